// round 5
// baseline (speedup 1.0000x reference)
#include <cuda_runtime.h>
#include <cuda_bf16.h>
#include <math.h>

#define N 8192
#define FIN 256
#define FOUT 64
#define RPB 16   // rows per block in main kernel

// Scratch (module globals -- no allocation allowed in kernel_launch)
__device__ float    g_Wh[(size_t)N * FOUT];
__device__ float    g_WhP[(size_t)N * FOUT];  // pair-packed layout
__device__ float2   g_epack[N];               // {exp(f_dst), exp(0.2 f_dst)}
__device__ float    g_fsrc[N];
__device__ unsigned g_gmax_enc;               // order-preserving encoded fp32 max

// packed f32x2 ops
#define FMA_F32X2(d, a, b) \
    asm("fma.rn.f32x2 %0, %1, %2, %0;" : "+l"(d) : "l"(a), "l"(b))
#define MUL_F32X2(d, a, b) \
    asm("mul.rn.f32x2 %0, %1, %2;" : "=l"(d) : "l"(a), "l"(b))

#define CP_ASYNC16(saddr, gptr) \
    asm volatile("cp.async.cg.shared.global [%0], [%1], 16;" ::"r"(saddr), "l"(gptr))
#define CP_COMMIT() asm volatile("cp.async.commit_group;")
#define CP_WAIT(n)  asm volatile("cp.async.wait_group %0;" ::"n"(n))

__device__ __forceinline__ unsigned enc_f(float x) {
    unsigned b = __float_as_uint(x);
    return (b & 0x80000000u) ? ~b : (b | 0x80000000u);
}
__device__ __forceinline__ float dec_f(unsigned k) {
    return __uint_as_float((k & 0x80000000u) ? (k & 0x7fffffffu) : ~k);
}

// ---------------------------------------------------------------------------
// Kernel A: Wh = h @ W  (+ pair-packed copy g_WhP). 16 rows/block, grid=512.
// Block 0 thread 0 also resets the gmax atomic for this launch.
// ---------------------------------------------------------------------------
__global__ __launch_bounds__(256) void wh_kernel(const float* __restrict__ h,
                                                 const float* __restrict__ W) {
    __shared__ float Ws[128][FOUT];
    if (blockIdx.x == 0 && threadIdx.x == 0) g_gmax_enc = 0u;

    const int f = threadIdx.x & 63;
    const int g = threadIdx.x >> 6;            // 0..3
    const int row0 = blockIdx.x * 16 + g * 4;  // 16 rows per block

    float acc[4];
#pragma unroll
    for (int r = 0; r < 4; r++) acc[r] = 0.f;

    for (int t = 0; t < 2; t++) {
        __syncthreads();
        for (int idx = threadIdx.x; idx < 128 * FOUT; idx += 256)
            (&Ws[0][0])[idx] = W[t * 128 * FOUT + idx];
        __syncthreads();
#pragma unroll
        for (int r = 0; r < 4; r++) {
            const float4* hrow =
                (const float4*)(h + (size_t)(row0 + r) * FIN + t * 128);
            float a0 = acc[r];
#pragma unroll
            for (int k4 = 0; k4 < 32; k4++) {
                float4 hv = hrow[k4];
                a0 += hv.x * Ws[k4 * 4 + 0][f];
                a0 += hv.y * Ws[k4 * 4 + 1][f];
                a0 += hv.z * Ws[k4 * 4 + 2][f];
                a0 += hv.w * Ws[k4 * 4 + 3][f];
            }
            acc[r] = a0;
        }
    }
#pragma unroll
    for (int r = 0; r < 4; r++) {
        const int row = row0 + r;
        g_Wh[(size_t)row * FOUT + f] = acc[r];
        const int jp = row >> 1;
        const size_t pidx =
            (size_t)jp * 128 + (f >> 1) * 4 + (f & 1) * 2 + (row & 1);
        g_WhP[pidx] = acc[r];
    }
}

// ---------------------------------------------------------------------------
// Kernel B: per-node scalars, factorized exps, fused global max of f_dst.
// ---------------------------------------------------------------------------
__global__ __launch_bounds__(256) void fvec_kernel(const float* __restrict__ a) {
    __shared__ unsigned smax[8];
    const int i = blockIdx.x * blockDim.x + threadIdx.x;
    const float4* w4 = (const float4*)(g_Wh + (size_t)i * FOUT);
    const float4* a4 = (const float4*)a;
    float s = 0.f, d = 0.f;
#pragma unroll
    for (int q = 0; q < 16; q++) {
        float4 v = w4[q];
        float4 as_ = a4[q];
        float4 ad = a4[16 + q];
        s += v.x * as_.x + v.y * as_.y + v.z * as_.z + v.w * as_.w;
        d += v.x * ad.x + v.y * ad.y + v.z * ad.z + v.w * ad.w;
    }
    g_fsrc[i] = s;
    g_epack[i] = make_float2(__expf(d), __expf(0.2f * d));

    // block max of d -> one atomic per block
    unsigned k = enc_f(d);
#pragma unroll
    for (int off = 16; off > 0; off >>= 1)
        k = max(k, __shfl_xor_sync(0xffffffffu, k, off));
    if ((threadIdx.x & 31) == 0) smax[threadIdx.x >> 5] = k;
    __syncthreads();
    if (threadIdx.x == 0) {
        unsigned m = smax[0];
#pragma unroll
        for (int w = 1; w < 8; w++) m = max(m, smax[w]);
        atomicMax(&g_gmax_enc, m);
    }
}

// ---------------------------------------------------------------------------
// Kernel D: fused masked softmax + (attention @ Wh) + ELU.
//   p_ij = adj ? max(A1_i*E1_j, A2_i*E2_j) : 0          (exp is monotone)
// Block = 16 rows, 8 warps over disjoint j-chunks of 32, 2 CTAs/SM.
// adj staged via cp.async double buffer; Wh pair-packed, register-double-
// buffered LDG.128; FFMA2 accumulation (2 j x 2 f per instruction).
// ---------------------------------------------------------------------------
__global__ __launch_bounds__(256, 2) void gat_main_kernel(
    const int* __restrict__ adj, float* __restrict__ out) {
    __shared__ float  sp[8][RPB][32];          // 16 KB  p [warp][row][jj]
    __shared__ int    sadj[8][2][RPB][32];     // 32 KB  adj double buffer
    __shared__ unsigned long long srowp[RPB];  // packed {A1, A2} per row
    __shared__ float  sacc4[4][RPB][64];       // 16 KB staged reduce
    __shared__ float  sl4[4][RPB];

    const int row0 = blockIdx.x * RPB;
    const int lane = threadIdx.x & 31;
    const int warp = threadIdx.x >> 5;

    if (threadIdx.x < RPB) {
        const float fs = g_fsrc[row0 + threadIdx.x];
        const float gmax = dec_f(g_gmax_enc);
        float M = fs + gmax;
        M = M > 0.f ? M : 0.2f * M;  // lrelu monotone -> valid row upper bound
        float2 A = make_float2(__expf(fs - M), __expf(0.2f * fs - M));
        srowp[threadIdx.x] = *(unsigned long long*)&A;
    }
    __syncthreads();

    unsigned long long acc0[RPB], acc1[RPB];  // packed over j-parity
    float l[RPB];
#pragma unroll
    for (int r = 0; r < RPB; r++) { acc0[r] = 0ull; acc1[r] = 0ull; l[r] = 0.f; }

    const int* adj_base = adj + (size_t)row0 * N;

    // cp.async issue helper geometry: lane covers rows {r4, r4+4, r4+8, r4+12},
    // 4 consecutive j starting at jq.
    const int r4 = lane >> 3;
    const int jq = (lane & 7) * 4;

    // prologue: stage chunk 0 into buffer 0
    {
        const int jb = warp * 32;
#pragma unroll
        for (int rr = 0; rr < 4; rr++) {
            const int r = rr * 4 + r4;
            const unsigned saddr =
                (unsigned)__cvta_generic_to_shared(&sadj[warp][0][r][jq]);
            CP_ASYNC16(saddr, adj_base + (size_t)r * N + jb + jq);
        }
        CP_COMMIT();
    }

    for (int c = 0; c < 32; c++) {
        const int jb = (c * 8 + warp) * 32;
        const int buf = c & 1;

        // stage next chunk into the other buffer
        if (c < 31) {
            const int jbn = jb + 256;
#pragma unroll
            for (int rr = 0; rr < 4; rr++) {
                const int r = rr * 4 + r4;
                const unsigned saddr = (unsigned)__cvta_generic_to_shared(
                    &sadj[warp][buf ^ 1][r][jq]);
                CP_ASYNC16(saddr, adj_base + (size_t)r * N + jbn + jq);
            }
            CP_COMMIT();
            CP_WAIT(1);  // chunk c's group complete
        } else {
            CP_WAIT(0);
        }
        __syncwarp();

        // ---- Phase A: p for this 32-j chunk, all 16 rows ----
        const float2 ep2 = g_epack[jb + lane];
        const unsigned long long ep = *(const unsigned long long*)&ep2;
#pragma unroll
        for (int r = 0; r < RPB; r++) {
            unsigned long long t;
            MUL_F32X2(t, srowp[r], ep);  // {A1*E1, A2*E2}
            float v = fmaxf(__uint_as_float((unsigned)t),
                            __uint_as_float((unsigned)(t >> 32)));
            v = sadj[warp][buf][r][lane] ? v : 0.f;
            l[r] += v;
            sp[warp][r][lane] = v;
        }
        __syncwarp();

        // ---- Phase B: packed FFMA2, register-double-buffered Wh loads ----
        const ulonglong2* wp =
            ((const ulonglong2*)g_WhP) + ((size_t)(jb >> 1)) * 32 + lane;
        ulonglong2 wa = wp[0];
        ulonglong2 wb = wp[32];
#pragma unroll
        for (int q2 = 0; q2 < 8; q2++) {
            ulonglong2 wa_n, wb_n;
            if (q2 < 7) {
                wa_n = wp[(size_t)(2 * q2 + 2) * 32];
                wb_n = wp[(size_t)(2 * q2 + 3) * 32];
            }
#pragma unroll
            for (int r = 0; r < RPB; r++) {
                const ulonglong2 pp = *(const ulonglong2*)&sp[warp][r][4 * q2];
                FMA_F32X2(acc0[r], pp.x, wa.x);
                FMA_F32X2(acc1[r], pp.x, wa.y);
                FMA_F32X2(acc0[r], pp.y, wb.x);
                FMA_F32X2(acc1[r], pp.y, wb.y);
            }
            if (q2 < 7) { wa = wa_n; wb = wb_n; }
        }
        __syncwarp();
    }

    // reduce l across lanes of the warp
#pragma unroll
    for (int r = 0; r < RPB; r++) {
#pragma unroll
        for (int off = 16; off > 0; off >>= 1)
            l[r] += __shfl_xor_sync(0xffffffffu, l[r], off);
    }

    // collapse packed halves -> per-f scalars
    float a0[RPB], a1[RPB];
#pragma unroll
    for (int r = 0; r < RPB; r++) {
        a0[r] = __uint_as_float((unsigned)acc0[r]) +
                __uint_as_float((unsigned)(acc0[r] >> 32));
        a1[r] = __uint_as_float((unsigned)acc1[r]) +
                __uint_as_float((unsigned)(acc1[r] >> 32));
    }

    // staged cross-warp reduction: warps 4..7 write, warps 0..3 add their own
    if (warp >= 4) {
#pragma unroll
        for (int r = 0; r < RPB; r++) {
            sacc4[warp - 4][r][2 * lane] = a0[r];
            sacc4[warp - 4][r][2 * lane + 1] = a1[r];
        }
        if (lane == 0) {
#pragma unroll
            for (int r = 0; r < RPB; r++) sl4[warp - 4][r] = l[r];
        }
    }
    __syncthreads();
    if (warp < 4) {
#pragma unroll
        for (int r = 0; r < RPB; r++) {
            sacc4[warp][r][2 * lane] += a0[r];
            sacc4[warp][r][2 * lane + 1] += a1[r];
        }
        if (lane == 0) {
#pragma unroll
            for (int r = 0; r < RPB; r++) sl4[warp][r] += l[r];
        }
    }
    __syncthreads();

    for (int idx = threadIdx.x; idx < RPB * 64; idx += 256) {
        const int r = idx >> 6, f = idx & 63;
        float s = 0.f, lt = 0.f;
#pragma unroll
        for (int w = 0; w < 4; w++) {
            s += sacc4[w][r][f];
            lt += sl4[w][r];
        }
        float o = s / lt;
        o = o > 0.f ? o : expm1f(o);  // ELU (alpha=1)
        out[(size_t)(row0 + r) * FOUT + f] = o;
    }
}

// ---------------------------------------------------------------------------
extern "C" void kernel_launch(void* const* d_in, const int* in_sizes, int n_in,
                              void* d_out, int out_size) {
    const float* h = (const float*)d_in[0];
    const int* adj = (const int*)d_in[1];
    const float* W = (const float*)d_in[2];
    const float* a = (const float*)d_in[3];
    float* out = (float*)d_out;

    wh_kernel<<<N / 16, 256>>>(h, W);
    fvec_kernel<<<N / 256, 256>>>(a);
    gat_main_kernel<<<N / RPB, 256>>>(adj, out);
}

// round 7
// speedup vs baseline: 2.3863x; 2.3863x over previous
#include <cuda_runtime.h>
#include <cuda_bf16.h>
#include <math.h>
#include <stdint.h>

#define N 8192
#define FIN 256
#define FOUT 64
#define NSPLIT 8    // j-splits per i-tile
#define NTILE 128   // i-rows per CTA
#define NSTEP 64    // K16 steps per CTA (1024 j per split)

// ---------------- device scratch ----------------
__device__ float    g_Wh[(size_t)N * FOUT];
__device__ uint4    g_Bfrag[512 * 2 * 4 * 32];  // tf32 B fragments, 2 MB
__device__ float    g_E1[N];                    // exp(f_dst)
__device__ float    g_E2[N];                    // exp(0.2 f_dst)
__device__ float    g_fsrc[N];
__device__ unsigned g_gmax_enc;
__device__ float    g_Dpart[NSPLIT][(size_t)N * FOUT];
__device__ float    g_lpart[NSPLIT][N];

// ---------------- helpers ----------------
#define CP_ASYNC16(saddr, gptr) \
    asm volatile("cp.async.cg.shared.global [%0], [%1], 16;" ::"r"(saddr), "l"(gptr))
#define CP_COMMIT() asm volatile("cp.async.commit_group;")
#define CP_WAIT(n)  asm volatile("cp.async.wait_group %0;" ::"n"(n))

__device__ __forceinline__ uint32_t f2tf32(float x) {
    uint32_t r;
    asm("cvt.rna.tf32.f32 %0, %1;" : "=r"(r) : "f"(x));
    return r;
}
__device__ __forceinline__ void mma_tf32(float* d, uint32_t a0, uint32_t a1,
                                         uint32_t a2, uint32_t a3, uint32_t b0,
                                         uint32_t b1) {
    asm volatile(
        "mma.sync.aligned.m16n8k8.row.col.f32.tf32.tf32.f32 "
        "{%0,%1,%2,%3}, {%4,%5,%6,%7}, {%8,%9}, {%0,%1,%2,%3};"
        : "+f"(d[0]), "+f"(d[1]), "+f"(d[2]), "+f"(d[3])
        : "r"(a0), "r"(a1), "r"(a2), "r"(a3), "r"(b0), "r"(b1));
}
__device__ __forceinline__ unsigned enc_f(float x) {
    unsigned b = __float_as_uint(x);
    return (b & 0x80000000u) ? ~b : (b | 0x80000000u);
}
__device__ __forceinline__ float dec_f(unsigned k) {
    return __uint_as_float((k & 0x80000000u) ? (k & 0x7fffffffu) : ~k);
}

// ---------------------------------------------------------------------------
// Kernel A: Wh = h @ W (8192x256 @ 256x64) -> g_Wh fp32.
// ---------------------------------------------------------------------------
__global__ __launch_bounds__(256, 3) void wh_kernel(const float* __restrict__ h,
                                                    const float* __restrict__ W) {
    __shared__ float Ws[128][FOUT];
    if (blockIdx.x == 0 && threadIdx.x == 0) g_gmax_enc = 0u;
    const int f = threadIdx.x & 63;
    const int g = threadIdx.x >> 6;
    const int row0 = blockIdx.x * 16 + g * 4;
    float acc[4] = {0.f, 0.f, 0.f, 0.f};
    for (int t = 0; t < 2; t++) {
        __syncthreads();
        for (int idx = threadIdx.x; idx < 128 * FOUT; idx += 256)
            (&Ws[0][0])[idx] = W[t * 128 * FOUT + idx];
        __syncthreads();
#pragma unroll
        for (int r = 0; r < 4; r++) {
            const float4* hrow =
                (const float4*)(h + (size_t)(row0 + r) * FIN + t * 128);
            float a0 = acc[r];
#pragma unroll 8
            for (int k4 = 0; k4 < 32; k4++) {
                float4 hv = hrow[k4];
                a0 += hv.x * Ws[k4 * 4 + 0][f];
                a0 += hv.y * Ws[k4 * 4 + 1][f];
                a0 += hv.z * Ws[k4 * 4 + 2][f];
                a0 += hv.w * Ws[k4 * 4 + 3][f];
            }
            acc[r] = a0;
        }
    }
#pragma unroll
    for (int r = 0; r < 4; r++)
        g_Wh[(size_t)(row0 + r) * FOUT + f] = acc[r];
}

// ---------------------------------------------------------------------------
// Kernel B: f_src, E1=exp(f_dst), E2=exp(0.2 f_dst), fused global max(f_dst).
// ---------------------------------------------------------------------------
__global__ __launch_bounds__(256) void fvec_kernel(const float* __restrict__ a) {
    __shared__ unsigned smax[8];
    const int i = blockIdx.x * blockDim.x + threadIdx.x;
    const float4* w4 = (const float4*)(g_Wh + (size_t)i * FOUT);
    const float4* a4 = (const float4*)a;
    float s = 0.f, d = 0.f;
#pragma unroll
    for (int q = 0; q < 16; q++) {
        float4 v = w4[q], as_ = a4[q], ad = a4[16 + q];
        s += v.x * as_.x + v.y * as_.y + v.z * as_.z + v.w * as_.w;
        d += v.x * ad.x + v.y * ad.y + v.z * ad.z + v.w * ad.w;
    }
    g_fsrc[i] = s;
    g_E1[i] = __expf(d);
    g_E2[i] = __expf(0.2f * d);
    unsigned k = enc_f(d);
#pragma unroll
    for (int off = 16; off > 0; off >>= 1)
        k = max(k, __shfl_xor_sync(0xffffffffu, k, off));
    if ((threadIdx.x & 31) == 0) smax[threadIdx.x >> 5] = k;
    __syncthreads();
    if (threadIdx.x == 0) {
        unsigned m = smax[0];
#pragma unroll
        for (int w = 1; w < 8; w++) m = max(m, smax[w]);
        atomicMax(&g_gmax_enc, m);
    }
}

// ---------------------------------------------------------------------------
// Kernel B2: build tf32 B fragments of Wh for mma.m16n8k8.
// g_Bfrag[((jblock16*2+kh)*4+ntp)*32+lane] = {b0(ntA),b1(ntA),b0(ntB),b1(ntB)}
// where b0 = Wh[j0+tc][f], b1 = Wh[j0+tc+4][f], f = nt*8 + (lane>>2).
// ---------------------------------------------------------------------------
__global__ __launch_bounds__(256) void bfrag_kernel() {
    const int wid = blockIdx.x * 8 + (threadIdx.x >> 5);  // 0..4095
    const int lane = threadIdx.x & 31;
    const int jblock = wid >> 3, kh = (wid >> 2) & 1, ntp = wid & 3;
    const int j0 = jblock * 16 + kh * 8;
    const int f0 = ntp * 16;
    const int g = lane >> 2, tc = lane & 3;
    uint4 b;
    b.x = f2tf32(g_Wh[(size_t)(j0 + tc) * FOUT + f0 + g]);
    b.y = f2tf32(g_Wh[(size_t)(j0 + tc + 4) * FOUT + f0 + g]);
    b.z = f2tf32(g_Wh[(size_t)(j0 + tc) * FOUT + f0 + 8 + g]);
    b.w = f2tf32(g_Wh[(size_t)(j0 + tc + 4) * FOUT + f0 + 8 + g]);
    g_Bfrag[(size_t)wid * 32 + lane] = b;
}

// ---------------------------------------------------------------------------
// Kernel C (main): D[128,64] += P[128,1024] @ Wh[1024,64] via mma.tf32.
//   p_ij = adj * max(A1_i*E1_j, A2_i*E2_j)  == adj * exp(lrelu(fs+fd) - M_i)
// adj: cp.async double-buffered smem tile (pad 20 -> conflict-free LDS).
// Warp w owns i-rows w*16..w*16+15; fragment thread (g=lane>>2, tc=lane&3).
// ---------------------------------------------------------------------------
#define SADJ(b, r, c) s_adj[(b) * 2560 + (r) * 20 + (c)]

__global__ __launch_bounds__(256, 2) void gat_mma_kernel(const int* __restrict__ adj) {
    __shared__ int    s_adj[2 * 2560];  // 20 KB, pad-20 rows
    __shared__ float2 s_E[1024];        // {E1, E2} for this split's j range
    __shared__ float  sA1[NTILE], sA2[NTILE];

    const int tid = threadIdx.x, lane = tid & 31, warp = tid >> 5;
    const int g = lane >> 2, tc = lane & 3;
    const int it = blockIdx.x >> 3, js = blockIdx.x & 7;
    const int row0 = it * NTILE, jbase = js * (NSTEP * 16);

    const int* adj_base = adj + (size_t)row0 * N + jbase;

    // cp.async geometry: flat 16B-segment id fi = tid*2+q: row = fi>>2,
    // segcol = (fi&3)*4 (tile rows are 16 ints = 4 segments).
    const int st_r0 = (tid * 2) >> 2, st_c0 = ((tid * 2) & 3) * 4;
    const int st_r1 = (tid * 2 + 1) >> 2, st_c1 = ((tid * 2 + 1) & 3) * 4;

    // prologue: stage step 0 into buffer 0
    {
        CP_ASYNC16((unsigned)__cvta_generic_to_shared(&SADJ(0, st_r0, st_c0)),
                   adj_base + (size_t)st_r0 * N + st_c0);
        CP_ASYNC16((unsigned)__cvta_generic_to_shared(&SADJ(0, st_r1, st_c1)),
                   adj_base + (size_t)st_r1 * N + st_c1);
        CP_COMMIT();
    }

    // stage E + per-row A1/A2
    for (int k = tid; k < 1024; k += 256)
        s_E[k] = make_float2(g_E1[jbase + k], g_E2[jbase + k]);
    if (tid < NTILE) {
        const float fs = g_fsrc[row0 + tid];
        float M = fs + dec_f(g_gmax_enc);
        M = M > 0.f ? M : 0.2f * M;  // lrelu monotone -> valid row upper bound
        sA1[tid] = __expf(fs - M);
        sA2[tid] = __expf(0.2f * fs - M);
    }
    __syncthreads();

    const int lr0 = warp * 16 + g, lr1 = lr0 + 8;
    const float A1r0 = sA1[lr0], A2r0 = sA2[lr0];
    const float A1r1 = sA1[lr1], A2r1 = sA2[lr1];

    float d[8][4];
#pragma unroll
    for (int nt = 0; nt < 8; nt++)
#pragma unroll
        for (int q = 0; q < 4; q++) d[nt][q] = 0.f;
    float l0 = 0.f, l1 = 0.f;

    for (int s = 0; s < NSTEP; s++) {
        const int buf = s & 1;
        if (s < NSTEP - 1) {  // stage next tile into other buffer
            const int jn = (s + 1) * 16;
            CP_ASYNC16(
                (unsigned)__cvta_generic_to_shared(&SADJ(buf ^ 1, st_r0, st_c0)),
                adj_base + (size_t)st_r0 * N + jn + st_c0);
            CP_ASYNC16(
                (unsigned)__cvta_generic_to_shared(&SADJ(buf ^ 1, st_r1, st_c1)),
                adj_base + (size_t)st_r1 * N + jn + st_c1);
            CP_COMMIT();
            CP_WAIT(1);
        } else {
            CP_WAIT(0);
        }
        __syncthreads();  // tile s visible; prior consumers done

        // p for 2 rows x 4 cols {tc, tc+4, tc+8, tc+12}
        const int jl = s * 16;
        float p[2][4];
#pragma unroll
        for (int cq = 0; cq < 4; cq++) {
            const int c = tc + cq * 4;
            const float2 e = s_E[jl + c];
            const int a0 = SADJ(buf, lr0, c);
            const int a1 = SADJ(buf, lr1, c);
            float v0 = fmaxf(A1r0 * e.x, A2r0 * e.y);
            float v1 = fmaxf(A1r1 * e.x, A2r1 * e.y);
            p[0][cq] = a0 ? v0 : 0.f;
            p[1][cq] = a1 ? v1 : 0.f;
        }
        l0 += p[0][0] + p[0][1] + p[0][2] + p[0][3];
        l1 += p[1][0] + p[1][1] + p[1][2] + p[1][3];

        const uint4* bp = &g_Bfrag[(size_t)((js * 64 + s) * 2) * 4 * 32 + lane];
#pragma unroll
        for (int kh = 0; kh < 2; kh++) {
            const uint32_t a0 = f2tf32(p[0][kh * 2]);
            const uint32_t a1 = f2tf32(p[1][kh * 2]);
            const uint32_t a2 = f2tf32(p[0][kh * 2 + 1]);
            const uint32_t a3 = f2tf32(p[1][kh * 2 + 1]);
            const uint4 B0 = bp[kh * 128 + 0];
            const uint4 B1 = bp[kh * 128 + 32];
            const uint4 B2 = bp[kh * 128 + 64];
            const uint4 B3 = bp[kh * 128 + 96];
            mma_tf32(d[0], a0, a1, a2, a3, B0.x, B0.y);
            mma_tf32(d[1], a0, a1, a2, a3, B0.z, B0.w);
            mma_tf32(d[2], a0, a1, a2, a3, B1.x, B1.y);
            mma_tf32(d[3], a0, a1, a2, a3, B1.z, B1.w);
            mma_tf32(d[4], a0, a1, a2, a3, B2.x, B2.y);
            mma_tf32(d[5], a0, a1, a2, a3, B2.z, B2.w);
            mma_tf32(d[6], a0, a1, a2, a3, B3.x, B3.y);
            mma_tf32(d[7], a0, a1, a2, a3, B3.z, B3.w);
        }
        __syncthreads();  // all consumers done before next overwrite
    }

    // write D partials: D[g][2tc..], D[g+8][2tc..] per n-tile
    const int gr0 = row0 + lr0, gr1 = row0 + lr1;
#pragma unroll
    for (int nt = 0; nt < 8; nt++) {
        const int f = nt * 8 + 2 * tc;
        *(float2*)&g_Dpart[js][(size_t)gr0 * FOUT + f] =
            make_float2(d[nt][0], d[nt][1]);
        *(float2*)&g_Dpart[js][(size_t)gr1 * FOUT + f] =
            make_float2(d[nt][2], d[nt][3]);
    }
    // row sums: reduce over tc (lanes g*4..g*4+3)
    l0 += __shfl_xor_sync(0xffffffffu, l0, 1);
    l0 += __shfl_xor_sync(0xffffffffu, l0, 2);
    l1 += __shfl_xor_sync(0xffffffffu, l1, 1);
    l1 += __shfl_xor_sync(0xffffffffu, l1, 2);
    if (tc == 0) {
        g_lpart[js][gr0] = l0;
        g_lpart[js][gr1] = l1;
    }
}

// ---------------------------------------------------------------------------
// Kernel E: combine partials, divide, ELU.
// ---------------------------------------------------------------------------
__global__ __launch_bounds__(256) void fixup_kernel(float* __restrict__ out) {
    const int idx = blockIdx.x * 256 + threadIdx.x;  // 131072 threads
    const int i = idx >> 4;
    const int f4 = (idx & 15) * 4;
    float4 acc = make_float4(0.f, 0.f, 0.f, 0.f);
    float l = 0.f;
#pragma unroll
    for (int js = 0; js < NSPLIT; js++) {
        const float4 dv = *(const float4*)&g_Dpart[js][(size_t)i * FOUT + f4];
        acc.x += dv.x; acc.y += dv.y; acc.z += dv.z; acc.w += dv.w;
        l += g_lpart[js][i];
    }
    const float inv = 1.f / l;
    float o0 = acc.x * inv, o1 = acc.y * inv, o2 = acc.z * inv, o3 = acc.w * inv;
    o0 = o0 > 0.f ? o0 : expm1f(o0);
    o1 = o1 > 0.f ? o1 : expm1f(o1);
    o2 = o2 > 0.f ? o2 : expm1f(o2);
    o3 = o3 > 0.f ? o3 : expm1f(o3);
    *(float4*)&out[(size_t)i * FOUT + f4] = make_float4(o0, o1, o2, o3);
}

// ---------------------------------------------------------------------------
extern "C" void kernel_launch(void* const* d_in, const int* in_sizes, int n_in,
                              void* d_out, int out_size) {
    const float* h = (const float*)d_in[0];
    const int* adj = (const int*)d_in[1];
    const float* W = (const float*)d_in[2];
    const float* a = (const float*)d_in[3];
    float* out = (float*)d_out;

    wh_kernel<<<N / 16, 256>>>(h, W);
    fvec_kernel<<<N / 256, 256>>>(a);
    bfrag_kernel<<<512, 256>>>();
    gat_mma_kernel<<<(N / NTILE) * NSPLIT, 256>>>(adj);
    fixup_kernel<<<N * 16 / 256, 256>>>(out);
}

// round 8
// speedup vs baseline: 2.5955x; 1.0877x over previous
#include <cuda_runtime.h>
#include <cuda_bf16.h>
#include <math.h>
#include <stdint.h>

#define N 8192
#define FIN 256
#define FOUT 64
#define NSPLIT 8    // j-splits per i-tile
#define NTILE 128   // i-rows per CTA
#define JSTEP 32    // j per pipeline step
#define NST 32      // steps per CTA (1024 j per split)
#define PIPE 3
#define ADJSTR 36   // padded adj row stride (ints) -> conflict-free LDS

// ---------------- device scratch ----------------
__device__ float    g_Wh[(size_t)N * FOUT];
__device__ uint4    g_Bfrag[512 * 2 * 4 * 32];  // tf32 B fragments, 2 MB
__device__ float    g_E1[N];
__device__ float    g_E2[N];
__device__ float    g_fsrc[N];
__device__ unsigned g_gmax_enc;
__device__ float    g_Dpart[NSPLIT][(size_t)N * FOUT];
__device__ float    g_lpart[NSPLIT][N];

// ---------------- helpers ----------------
#define CP_ASYNC16(saddr, gptr) \
    asm volatile("cp.async.cg.shared.global [%0], [%1], 16;" ::"r"(saddr), "l"(gptr))
#define CP_COMMIT() asm volatile("cp.async.commit_group;")
#define CP_WAIT(n)  asm volatile("cp.async.wait_group %0;" ::"n"(n))

__device__ __forceinline__ uint32_t f2tf32(float x) {
    uint32_t r;
    asm("cvt.rna.tf32.f32 %0, %1;" : "=r"(r) : "f"(x));
    return r;
}
__device__ __forceinline__ void mma_tf32(float* d, uint32_t a0, uint32_t a1,
                                         uint32_t a2, uint32_t a3, uint32_t b0,
                                         uint32_t b1) {
    asm volatile(
        "mma.sync.aligned.m16n8k8.row.col.f32.tf32.tf32.f32 "
        "{%0,%1,%2,%3}, {%4,%5,%6,%7}, {%8,%9}, {%0,%1,%2,%3};"
        : "+f"(d[0]), "+f"(d[1]), "+f"(d[2]), "+f"(d[3])
        : "r"(a0), "r"(a1), "r"(a2), "r"(a3), "r"(b0), "r"(b1));
}
__device__ __forceinline__ unsigned enc_f(float x) {
    unsigned b = __float_as_uint(x);
    return (b & 0x80000000u) ? ~b : (b | 0x80000000u);
}
__device__ __forceinline__ float dec_f(unsigned k) {
    return __uint_as_float((k & 0x80000000u) ? (k & 0x7fffffffu) : ~k);
}

// ---------------------------------------------------------------------------
// Kernel A: Wh = h @ W. k-outer/r-inner: each Ws value reused across 4 rows.
// ---------------------------------------------------------------------------
__global__ __launch_bounds__(256, 4) void wh_kernel(const float* __restrict__ h,
                                                    const float* __restrict__ W) {
    __shared__ float Ws[128][FOUT];
    if (blockIdx.x == 0 && threadIdx.x == 0) g_gmax_enc = 0u;
    const int f = threadIdx.x & 63;
    const int g = threadIdx.x >> 6;
    const int row0 = blockIdx.x * 16 + g * 4;
    float acc0 = 0.f, acc1 = 0.f, acc2 = 0.f, acc3 = 0.f;
    for (int t = 0; t < 2; t++) {
        __syncthreads();
        for (int idx = threadIdx.x; idx < 128 * FOUT; idx += 256)
            (&Ws[0][0])[idx] = W[t * 128 * FOUT + idx];
        __syncthreads();
        const float4* h0 = (const float4*)(h + (size_t)(row0 + 0) * FIN + t * 128);
        const float4* h1 = (const float4*)(h + (size_t)(row0 + 1) * FIN + t * 128);
        const float4* h2 = (const float4*)(h + (size_t)(row0 + 2) * FIN + t * 128);
        const float4* h3 = (const float4*)(h + (size_t)(row0 + 3) * FIN + t * 128);
#pragma unroll 8
        for (int k4 = 0; k4 < 32; k4++) {
            const float4 v0 = h0[k4], v1 = h1[k4], v2 = h2[k4], v3 = h3[k4];
            const float w0 = Ws[k4 * 4 + 0][f];
            const float w1 = Ws[k4 * 4 + 1][f];
            const float w2 = Ws[k4 * 4 + 2][f];
            const float w3 = Ws[k4 * 4 + 3][f];
            acc0 += v0.x * w0 + v0.y * w1 + v0.z * w2 + v0.w * w3;
            acc1 += v1.x * w0 + v1.y * w1 + v1.z * w2 + v1.w * w3;
            acc2 += v2.x * w0 + v2.y * w1 + v2.z * w2 + v2.w * w3;
            acc3 += v3.x * w0 + v3.y * w1 + v3.z * w2 + v3.w * w3;
        }
    }
    g_Wh[(size_t)(row0 + 0) * FOUT + f] = acc0;
    g_Wh[(size_t)(row0 + 1) * FOUT + f] = acc1;
    g_Wh[(size_t)(row0 + 2) * FOUT + f] = acc2;
    g_Wh[(size_t)(row0 + 3) * FOUT + f] = acc3;
}

// ---------------------------------------------------------------------------
// Kernel B: f_src, E1=exp(f_dst), E2=exp(0.2 f_dst), fused global max(f_dst).
// ---------------------------------------------------------------------------
__global__ __launch_bounds__(256) void fvec_kernel(const float* __restrict__ a) {
    __shared__ unsigned smax[8];
    const int i = blockIdx.x * blockDim.x + threadIdx.x;
    const float4* w4 = (const float4*)(g_Wh + (size_t)i * FOUT);
    const float4* a4 = (const float4*)a;
    float s = 0.f, d = 0.f;
#pragma unroll
    for (int q = 0; q < 16; q++) {
        float4 v = w4[q], as_ = a4[q], ad = a4[16 + q];
        s += v.x * as_.x + v.y * as_.y + v.z * as_.z + v.w * as_.w;
        d += v.x * ad.x + v.y * ad.y + v.z * ad.z + v.w * ad.w;
    }
    g_fsrc[i] = s;
    g_E1[i] = __expf(d);
    g_E2[i] = __expf(0.2f * d);
    unsigned k = enc_f(d);
#pragma unroll
    for (int off = 16; off > 0; off >>= 1)
        k = max(k, __shfl_xor_sync(0xffffffffu, k, off));
    if ((threadIdx.x & 31) == 0) smax[threadIdx.x >> 5] = k;
    __syncthreads();
    if (threadIdx.x == 0) {
        unsigned m = smax[0];
#pragma unroll
        for (int w = 1; w < 8; w++) m = max(m, smax[w]);
        atomicMax(&g_gmax_enc, m);
    }
}

// ---------------------------------------------------------------------------
// Kernel B2: build tf32 B fragments of Wh for mma.m16n8k8 (as R7, passing).
// ---------------------------------------------------------------------------
__global__ __launch_bounds__(256) void bfrag_kernel() {
    const int wid = blockIdx.x * 8 + (threadIdx.x >> 5);  // 0..4095
    const int lane = threadIdx.x & 31;
    const int jblock = wid >> 3, kh = (wid >> 2) & 1, ntp = wid & 3;
    const int j0 = jblock * 16 + kh * 8;
    const int f0 = ntp * 16;
    const int g = lane >> 2, tc = lane & 3;
    uint4 b;
    b.x = f2tf32(g_Wh[(size_t)(j0 + tc) * FOUT + f0 + g]);
    b.y = f2tf32(g_Wh[(size_t)(j0 + tc + 4) * FOUT + f0 + g]);
    b.z = f2tf32(g_Wh[(size_t)(j0 + tc) * FOUT + f0 + 8 + g]);
    b.w = f2tf32(g_Wh[(size_t)(j0 + tc + 4) * FOUT + f0 + 8 + g]);
    g_Bfrag[(size_t)wid * 32 + lane] = b;
}

// ---------------------------------------------------------------------------
// Kernel C (main): D[128,64] += P[128,1024] @ Wh[1024,64] via mma.tf32.
// adj: PIPE=3 cp.async pipeline of 128x32 tiles (2 groups in flight).
// One __syncthreads per step: the wait+barrier proves tile s ready AND all
// consumers of tile s-1 done, so staging s+2 into buffer (s-1)%3 is safe.
// ---------------------------------------------------------------------------
#define SADJ(b, r, c) s_adj[(b) * (128 * ADJSTR) + (r) * ADJSTR + (c)]

__global__ __launch_bounds__(256, 2) void gat_mma_kernel(const int* __restrict__ adj) {
    __shared__ int    s_adj[PIPE * 128 * ADJSTR];  // 54 KB
    __shared__ float2 s_E[1024];                   // 8 KB
    __shared__ float  sA1[NTILE], sA2[NTILE];

    const int tid = threadIdx.x, lane = tid & 31, warp = tid >> 5;
    const int g = lane >> 2, tc = lane & 3;
    const int it = blockIdx.x >> 3, js = blockIdx.x & 7;
    const int row0 = it * NTILE, jbase = js * (NST * JSTEP);

    const int* adj_base = adj + (size_t)row0 * N + jbase;

    // staging geometry: thread covers 4 consecutive 16B segments (64B)
    // of row strow, cols [stcol, stcol+16).
    const int strow = tid >> 1;
    const int stcol = (tid & 1) * 16;
    const int* gsrc = adj_base + (size_t)strow * N + stcol;
    const uint32_t sdst0 =
        (uint32_t)__cvta_generic_to_shared(&SADJ(0, strow, stcol));

    // prologue: stage steps 0 and 1
#pragma unroll
    for (int s = 0; s < PIPE - 1; s++) {
#pragma unroll
        for (int q = 0; q < 4; q++)
            CP_ASYNC16(sdst0 + (s * 128 * ADJSTR) * 4 + q * 16,
                       gsrc + s * JSTEP + q * 4);
        CP_COMMIT();
    }

    // stage E and per-row A1/A2
    for (int k = tid; k < 1024; k += 256)
        s_E[k] = make_float2(g_E1[jbase + k], g_E2[jbase + k]);
    if (tid < NTILE) {
        const float fs = g_fsrc[row0 + tid];
        float M = fs + dec_f(g_gmax_enc);
        M = M > 0.f ? M : 0.2f * M;  // lrelu monotone -> valid row upper bound
        sA1[tid] = __expf(fs - M);
        sA2[tid] = __expf(0.2f * fs - M);
    }
    __syncthreads();

    const int lr0 = warp * 16 + g, lr1 = lr0 + 8;
    const float A1r0 = sA1[lr0], A2r0 = sA2[lr0];
    const float A1r1 = sA1[lr1], A2r1 = sA2[lr1];

    float d[8][4];
#pragma unroll
    for (int nt = 0; nt < 8; nt++)
#pragma unroll
        for (int q = 0; q < 4; q++) d[nt][q] = 0.f;
    float l0 = 0.f, l1 = 0.f;

    for (int s = 0; s < NST; s++) {
        const int buf = s % PIPE;
        if (s < NST - 1) CP_WAIT(PIPE - 2);
        else             CP_WAIT(0);
        __syncthreads();  // tile s visible; tile s-1 fully consumed

        // stage step s+2 into buffer (s+2)%PIPE == (s-1)%PIPE
        if (s + PIPE - 1 < NST) {
            const int sn = s + PIPE - 1;
            const uint32_t sd = sdst0 + ((sn % PIPE) * 128 * ADJSTR) * 4;
#pragma unroll
            for (int q = 0; q < 4; q++)
                CP_ASYNC16(sd + q * 16, gsrc + sn * JSTEP + q * 4);
            CP_COMMIT();
        }

        // ---- p for 2 rows x 8 cols {tc + 4cq} ----
        const int jl = s * JSTEP;
        float p0[8], p1[8];
#pragma unroll
        for (int cq = 0; cq < 8; cq++) {
            const int c = tc + cq * 4;
            const float2 e = s_E[jl + c];
            const int a0 = SADJ(buf, lr0, c);
            const int a1 = SADJ(buf, lr1, c);
            const float v0 = fmaxf(A1r0 * e.x, A2r0 * e.y);
            const float v1 = fmaxf(A1r1 * e.x, A2r1 * e.y);
            p0[cq] = a0 ? v0 : 0.f;
            p1[cq] = a1 ? v1 : 0.f;
            l0 += p0[cq];
            l1 += p1[cq];
        }

        // ---- 4 K-groups of 8: MMAs ----
#pragma unroll
        for (int kk = 0; kk < 4; kk++) {
            const int jblock = js * 64 + 2 * s + (kk >> 1);
            const int kh = kk & 1;
            const uint4* bp =
                &g_Bfrag[(size_t)((jblock * 2 + kh) * 4) * 32 + lane];
            const uint32_t a0 = f2tf32(p0[kk * 2]);
            const uint32_t a1 = f2tf32(p1[kk * 2]);
            const uint32_t a2 = f2tf32(p0[kk * 2 + 1]);
            const uint32_t a3 = f2tf32(p1[kk * 2 + 1]);
            const uint4 B0 = bp[0];
            const uint4 B1 = bp[32];
            const uint4 B2 = bp[64];
            const uint4 B3 = bp[96];
            mma_tf32(d[0], a0, a1, a2, a3, B0.x, B0.y);
            mma_tf32(d[1], a0, a1, a2, a3, B0.z, B0.w);
            mma_tf32(d[2], a0, a1, a2, a3, B1.x, B1.y);
            mma_tf32(d[3], a0, a1, a2, a3, B1.z, B1.w);
            mma_tf32(d[4], a0, a1, a2, a3, B2.x, B2.y);
            mma_tf32(d[5], a0, a1, a2, a3, B2.z, B2.w);
            mma_tf32(d[6], a0, a1, a2, a3, B3.x, B3.y);
            mma_tf32(d[7], a0, a1, a2, a3, B3.z, B3.w);
        }
    }

    // write D partials
    const int gr0 = row0 + lr0, gr1 = row0 + lr1;
#pragma unroll
    for (int nt = 0; nt < 8; nt++) {
        const int f = nt * 8 + 2 * tc;
        *(float2*)&g_Dpart[js][(size_t)gr0 * FOUT + f] =
            make_float2(d[nt][0], d[nt][1]);
        *(float2*)&g_Dpart[js][(size_t)gr1 * FOUT + f] =
            make_float2(d[nt][2], d[nt][3]);
    }
    // row sums: reduce over tc (lanes g*4..g*4+3)
    l0 += __shfl_xor_sync(0xffffffffu, l0, 1);
    l0 += __shfl_xor_sync(0xffffffffu, l0, 2);
    l1 += __shfl_xor_sync(0xffffffffu, l1, 1);
    l1 += __shfl_xor_sync(0xffffffffu, l1, 2);
    if (tc == 0) {
        g_lpart[js][gr0] = l0;
        g_lpart[js][gr1] = l1;
    }
}

// ---------------------------------------------------------------------------
// Kernel E: combine partials, divide, ELU.
// ---------------------------------------------------------------------------
__global__ __launch_bounds__(256) void fixup_kernel(float* __restrict__ out) {
    const int idx = blockIdx.x * 256 + threadIdx.x;
    const int i = idx >> 4;
    const int f4 = (idx & 15) * 4;
    float4 acc = make_float4(0.f, 0.f, 0.f, 0.f);
    float l = 0.f;
#pragma unroll
    for (int js = 0; js < NSPLIT; js++) {
        const float4 dv = *(const float4*)&g_Dpart[js][(size_t)i * FOUT + f4];
        acc.x += dv.x; acc.y += dv.y; acc.z += dv.z; acc.w += dv.w;
        l += g_lpart[js][i];
    }
    const float inv = 1.f / l;
    float o0 = acc.x * inv, o1 = acc.y * inv, o2 = acc.z * inv, o3 = acc.w * inv;
    o0 = o0 > 0.f ? o0 : expm1f(o0);
    o1 = o1 > 0.f ? o1 : expm1f(o1);
    o2 = o2 > 0.f ? o2 : expm1f(o2);
    o3 = o3 > 0.f ? o3 : expm1f(o3);
    *(float4*)&out[(size_t)i * FOUT + f4] = make_float4(o0, o1, o2, o3);
}

// ---------------------------------------------------------------------------
extern "C" void kernel_launch(void* const* d_in, const int* in_sizes, int n_in,
                              void* d_out, int out_size) {
    const float* h = (const float*)d_in[0];
    const int* adj = (const int*)d_in[1];
    const float* W = (const float*)d_in[2];
    const float* a = (const float*)d_in[3];
    float* out = (float*)d_out;

    wh_kernel<<<N / 16, 256>>>(h, W);
    fvec_kernel<<<N / 256, 256>>>(a);
    bfrag_kernel<<<512, 256>>>();
    gat_mma_kernel<<<(N / NTILE) * NSPLIT, 256>>>(adj);
    fixup_kernel<<<N * 16 / 256, 256>>>(out);
}

// round 9
// speedup vs baseline: 3.2126x; 1.2378x over previous
#include <cuda_runtime.h>
#include <cuda_bf16.h>
#include <math.h>
#include <stdint.h>

#define N 8192
#define FIN 256
#define FOUT 64
#define NSPLIT 8    // j-splits per i-tile
#define NTILE 128   // i-rows per CTA
#define JSTEP 32    // j per pipeline step
#define NST 32      // steps per CTA (1024 j per split)
#define PIPE 4      // per-warp ring depth
#define WSTR 36     // padded row stride (ints) -> conflict-free LDS
#define WBUF (16 * WSTR)

// ---------------- device scratch ----------------
__device__ float    g_Wh[(size_t)N * FOUT];
__device__ uint4    g_Bfrag[512 * 2 * 4 * 32];  // tf32 B fragments, 2 MB
__device__ float    g_E1[N];
__device__ float    g_E2[N];
__device__ float    g_fsrc[N];
__device__ unsigned g_gmax_enc;
__device__ float    g_Dpart[NSPLIT][(size_t)N * FOUT];
__device__ float    g_lpart[NSPLIT][N];

// ---------------- helpers ----------------
#define CP_ASYNC16(saddr, gptr) \
    asm volatile("cp.async.cg.shared.global [%0], [%1], 16;" ::"r"(saddr), "l"(gptr))
#define CP_COMMIT() asm volatile("cp.async.commit_group;")
#define CP_WAIT(n)  asm volatile("cp.async.wait_group %0;" ::"n"(n))

__device__ __forceinline__ uint32_t f2tf32(float x) {
    uint32_t r;
    asm("cvt.rna.tf32.f32 %0, %1;" : "=r"(r) : "f"(x));
    return r;
}
__device__ __forceinline__ void mma_tf32(float* d, uint32_t a0, uint32_t a1,
                                         uint32_t a2, uint32_t a3, uint32_t b0,
                                         uint32_t b1) {
    asm volatile(
        "mma.sync.aligned.m16n8k8.row.col.f32.tf32.tf32.f32 "
        "{%0,%1,%2,%3}, {%4,%5,%6,%7}, {%8,%9}, {%0,%1,%2,%3};"
        : "+f"(d[0]), "+f"(d[1]), "+f"(d[2]), "+f"(d[3])
        : "r"(a0), "r"(a1), "r"(a2), "r"(a3), "r"(b0), "r"(b1));
}
__device__ __forceinline__ unsigned enc_f(float x) {
    unsigned b = __float_as_uint(x);
    return (b & 0x80000000u) ? ~b : (b | 0x80000000u);
}
__device__ __forceinline__ float dec_f(unsigned k) {
    return __uint_as_float((k & 0x80000000u) ? (k & 0x7fffffffu) : ~k);
}

// ---------------------------------------------------------------------------
// Kernel A: Wh = h @ W. k-outer/r-inner (Ws reuse across 4 rows).
// ---------------------------------------------------------------------------
__global__ __launch_bounds__(256, 4) void wh_kernel(const float* __restrict__ h,
                                                    const float* __restrict__ W) {
    __shared__ float Ws[128][FOUT];
    if (blockIdx.x == 0 && threadIdx.x == 0) g_gmax_enc = 0u;
    const int f = threadIdx.x & 63;
    const int g = threadIdx.x >> 6;
    const int row0 = blockIdx.x * 16 + g * 4;
    float acc0 = 0.f, acc1 = 0.f, acc2 = 0.f, acc3 = 0.f;
    for (int t = 0; t < 2; t++) {
        __syncthreads();
        for (int idx = threadIdx.x; idx < 128 * FOUT; idx += 256)
            (&Ws[0][0])[idx] = W[t * 128 * FOUT + idx];
        __syncthreads();
        const float4* h0 = (const float4*)(h + (size_t)(row0 + 0) * FIN + t * 128);
        const float4* h1 = (const float4*)(h + (size_t)(row0 + 1) * FIN + t * 128);
        const float4* h2 = (const float4*)(h + (size_t)(row0 + 2) * FIN + t * 128);
        const float4* h3 = (const float4*)(h + (size_t)(row0 + 3) * FIN + t * 128);
#pragma unroll 8
        for (int k4 = 0; k4 < 32; k4++) {
            const float4 v0 = h0[k4], v1 = h1[k4], v2 = h2[k4], v3 = h3[k4];
            const float w0 = Ws[k4 * 4 + 0][f];
            const float w1 = Ws[k4 * 4 + 1][f];
            const float w2 = Ws[k4 * 4 + 2][f];
            const float w3 = Ws[k4 * 4 + 3][f];
            acc0 += v0.x * w0 + v0.y * w1 + v0.z * w2 + v0.w * w3;
            acc1 += v1.x * w0 + v1.y * w1 + v1.z * w2 + v1.w * w3;
            acc2 += v2.x * w0 + v2.y * w1 + v2.z * w2 + v2.w * w3;
            acc3 += v3.x * w0 + v3.y * w1 + v3.z * w2 + v3.w * w3;
        }
    }
    g_Wh[(size_t)(row0 + 0) * FOUT + f] = acc0;
    g_Wh[(size_t)(row0 + 1) * FOUT + f] = acc1;
    g_Wh[(size_t)(row0 + 2) * FOUT + f] = acc2;
    g_Wh[(size_t)(row0 + 3) * FOUT + f] = acc3;
}

// ---------------------------------------------------------------------------
// Kernel B: f_src, E1=exp(f_dst), E2=exp(0.2 f_dst), fused global max(f_dst).
// ---------------------------------------------------------------------------
__global__ __launch_bounds__(256) void fvec_kernel(const float* __restrict__ a) {
    __shared__ unsigned smax[8];
    const int i = blockIdx.x * blockDim.x + threadIdx.x;
    const float4* w4 = (const float4*)(g_Wh + (size_t)i * FOUT);
    const float4* a4 = (const float4*)a;
    float s = 0.f, d = 0.f;
#pragma unroll
    for (int q = 0; q < 16; q++) {
        float4 v = w4[q], as_ = a4[q], ad = a4[16 + q];
        s += v.x * as_.x + v.y * as_.y + v.z * as_.z + v.w * as_.w;
        d += v.x * ad.x + v.y * ad.y + v.z * ad.z + v.w * ad.w;
    }
    g_fsrc[i] = s;
    g_E1[i] = __expf(d);
    g_E2[i] = __expf(0.2f * d);
    unsigned k = enc_f(d);
#pragma unroll
    for (int off = 16; off > 0; off >>= 1)
        k = max(k, __shfl_xor_sync(0xffffffffu, k, off));
    if ((threadIdx.x & 31) == 0) smax[threadIdx.x >> 5] = k;
    __syncthreads();
    if (threadIdx.x == 0) {
        unsigned m = smax[0];
#pragma unroll
        for (int w = 1; w < 8; w++) m = max(m, smax[w]);
        atomicMax(&g_gmax_enc, m);
    }
}

// ---------------------------------------------------------------------------
// Kernel B2: build tf32 B fragments of Wh for mma.m16n8k8.
// ---------------------------------------------------------------------------
__global__ __launch_bounds__(256) void bfrag_kernel() {
    const int wid = blockIdx.x * 8 + (threadIdx.x >> 5);  // 0..4095
    const int lane = threadIdx.x & 31;
    const int jblock = wid >> 3, kh = (wid >> 2) & 1, ntp = wid & 3;
    const int j0 = jblock * 16 + kh * 8;
    const int f0 = ntp * 16;
    const int g = lane >> 2, tc = lane & 3;
    uint4 b;
    b.x = f2tf32(g_Wh[(size_t)(j0 + tc) * FOUT + f0 + g]);
    b.y = f2tf32(g_Wh[(size_t)(j0 + tc + 4) * FOUT + f0 + g]);
    b.z = f2tf32(g_Wh[(size_t)(j0 + tc) * FOUT + f0 + 8 + g]);
    b.w = f2tf32(g_Wh[(size_t)(j0 + tc + 4) * FOUT + f0 + 8 + g]);
    g_Bfrag[(size_t)wid * 32 + lane] = b;
}

// ---------------------------------------------------------------------------
// Kernel C (main): D[128,64] += P[128,1024] @ Wh[1024,64] via mma.tf32.
// PER-WARP adj pipelines: warp w owns i-rows w*16..w*16+15 and stages its own
// 16x32 adj tiles in a PIPE=4 cp.async ring. No __syncthreads in the loop —
// only cp.async.wait_group + __syncwarp. Empty commit_group in tail
// iterations keeps wait counts exact.
// ---------------------------------------------------------------------------
#define SADJW(w, b, r, c) \
    s_adj[(w) * (PIPE * WBUF) + (b) * WBUF + (r) * WSTR + (c)]

__global__ __launch_bounds__(256, 2) void gat_mma_kernel(const int* __restrict__ adj) {
    __shared__ int    s_adj[8 * PIPE * WBUF];  // 72 KB
    __shared__ float2 s_E[1024];               // 8 KB
    __shared__ float  sA1[NTILE], sA2[NTILE];

    const int tid = threadIdx.x, lane = tid & 31, warp = tid >> 5;
    const int g = lane >> 2, tc = lane & 3;
    const int it = blockIdx.x >> 3, js = blockIdx.x & 7;
    const int row0 = it * NTILE, jbase = js * (NST * JSTEP);

    // per-warp staging geometry: lane covers row strow (0..15), 16 ints
    // starting at stcol, as 4 x 16B segments.
    const int strow = lane >> 1, stcol = (lane & 1) * 16;
    const int* gsrc = adj + (size_t)(row0 + warp * 16 + strow) * N + jbase + stcol;
    const uint32_t sw_lane =
        (uint32_t)__cvta_generic_to_shared(&SADJW(warp, 0, strow, stcol));

    // prologue: stage tiles 0..PIPE-2
#pragma unroll
    for (int t = 0; t < PIPE - 1; t++) {
        const uint32_t sd = sw_lane + (uint32_t)(t * WBUF) * 4u;
#pragma unroll
        for (int q = 0; q < 4; q++)
            CP_ASYNC16(sd + q * 16, gsrc + t * JSTEP + q * 4);
        CP_COMMIT();
    }

    // stage E and per-row A1/A2 (CTA-wide, once)
    for (int k = tid; k < 1024; k += 256)
        s_E[k] = make_float2(g_E1[jbase + k], g_E2[jbase + k]);
    if (tid < NTILE) {
        const float fs = g_fsrc[row0 + tid];
        float M = fs + dec_f(g_gmax_enc);
        M = M > 0.f ? M : 0.2f * M;  // lrelu monotone -> valid row upper bound
        sA1[tid] = __expf(fs - M);
        sA2[tid] = __expf(0.2f * fs - M);
    }
    __syncthreads();

    const int lr0 = warp * 16 + g, lr1 = lr0 + 8;
    const float A1r0 = sA1[lr0], A2r0 = sA2[lr0];
    const float A1r1 = sA1[lr1], A2r1 = sA2[lr1];

    float d[8][4];
#pragma unroll
    for (int nt = 0; nt < 8; nt++)
#pragma unroll
        for (int q = 0; q < 4; q++) d[nt][q] = 0.f;
    float l0 = 0.f, l1 = 0.f;

    for (int s = 0; s < NST; s++) {
        const int buf = s % PIPE;
        CP_WAIT(PIPE - 2);  // tile s arrived (later groups may be in flight)
        __syncwarp();

        // stage tile s+PIPE-1 into ring slot (s-1)%PIPE (consumed last iter);
        // ALWAYS commit a group so wait counts stay exact.
        if (s + PIPE - 1 < NST) {
            const int t = s + PIPE - 1;
            const uint32_t sd = sw_lane + (uint32_t)((t % PIPE) * WBUF) * 4u;
#pragma unroll
            for (int q = 0; q < 4; q++)
                CP_ASYNC16(sd + q * 16, gsrc + t * JSTEP + q * 4);
        }
        CP_COMMIT();

        // ---- p for 2 rows x 8 cols {tc + 4cq} ----
        const int jl = s * JSTEP;
        float p0[8], p1[8];
#pragma unroll
        for (int cq = 0; cq < 8; cq++) {
            const int c = tc + cq * 4;
            const float2 e = s_E[jl + c];
            const int a0 = SADJW(warp, buf, g, c);
            const int a1 = SADJW(warp, buf, g + 8, c);
            const float v0 = fmaxf(A1r0 * e.x, A2r0 * e.y);
            const float v1 = fmaxf(A1r1 * e.x, A2r1 * e.y);
            p0[cq] = a0 ? v0 : 0.f;
            p1[cq] = a1 ? v1 : 0.f;
            l0 += p0[cq];
            l1 += p1[cq];
        }

        // ---- 4 K-groups of 8 j: MMAs (B fragments from L2) ----
#pragma unroll
        for (int kk = 0; kk < 4; kk++) {
            const int jblock = js * 64 + 2 * s + (kk >> 1);
            const int kh = kk & 1;
            const uint4* bp =
                &g_Bfrag[(size_t)((jblock * 2 + kh) * 4) * 32 + lane];
            const uint32_t a0 = f2tf32(p0[kk * 2]);
            const uint32_t a1 = f2tf32(p1[kk * 2]);
            const uint32_t a2 = f2tf32(p0[kk * 2 + 1]);
            const uint32_t a3 = f2tf32(p1[kk * 2 + 1]);
            const uint4 B0 = bp[0];
            const uint4 B1 = bp[32];
            const uint4 B2 = bp[64];
            const uint4 B3 = bp[96];
            mma_tf32(d[0], a0, a1, a2, a3, B0.x, B0.y);
            mma_tf32(d[1], a0, a1, a2, a3, B0.z, B0.w);
            mma_tf32(d[2], a0, a1, a2, a3, B1.x, B1.y);
            mma_tf32(d[3], a0, a1, a2, a3, B1.z, B1.w);
            mma_tf32(d[4], a0, a1, a2, a3, B2.x, B2.y);
            mma_tf32(d[5], a0, a1, a2, a3, B2.z, B2.w);
            mma_tf32(d[6], a0, a1, a2, a3, B3.x, B3.y);
            mma_tf32(d[7], a0, a1, a2, a3, B3.z, B3.w);
        }
    }

    // write D partials
    const int gr0 = row0 + lr0, gr1 = row0 + lr1;
#pragma unroll
    for (int nt = 0; nt < 8; nt++) {
        const int f = nt * 8 + 2 * tc;
        *(float2*)&g_Dpart[js][(size_t)gr0 * FOUT + f] =
            make_float2(d[nt][0], d[nt][1]);
        *(float2*)&g_Dpart[js][(size_t)gr1 * FOUT + f] =
            make_float2(d[nt][2], d[nt][3]);
    }
    // row sums: reduce over tc (lanes g*4..g*4+3)
    l0 += __shfl_xor_sync(0xffffffffu, l0, 1);
    l0 += __shfl_xor_sync(0xffffffffu, l0, 2);
    l1 += __shfl_xor_sync(0xffffffffu, l1, 1);
    l1 += __shfl_xor_sync(0xffffffffu, l1, 2);
    if (tc == 0) {
        g_lpart[js][gr0] = l0;
        g_lpart[js][gr1] = l1;
    }
}

// ---------------------------------------------------------------------------
// Kernel E: combine partials, divide, ELU.
// ---------------------------------------------------------------------------
__global__ __launch_bounds__(256) void fixup_kernel(float* __restrict__ out) {
    const int idx = blockIdx.x * 256 + threadIdx.x;
    const int i = idx >> 4;
    const int f4 = (idx & 15) * 4;
    float4 acc = make_float4(0.f, 0.f, 0.f, 0.f);
    float l = 0.f;
#pragma unroll
    for (int js = 0; js < NSPLIT; js++) {
        const float4 dv = *(const float4*)&g_Dpart[js][(size_t)i * FOUT + f4];
        acc.x += dv.x; acc.y += dv.y; acc.z += dv.z; acc.w += dv.w;
        l += g_lpart[js][i];
    }
    const float inv = 1.f / l;
    float o0 = acc.x * inv, o1 = acc.y * inv, o2 = acc.z * inv, o3 = acc.w * inv;
    o0 = o0 > 0.f ? o0 : expm1f(o0);
    o1 = o1 > 0.f ? o1 : expm1f(o1);
    o2 = o2 > 0.f ? o2 : expm1f(o2);
    o3 = o3 > 0.f ? o3 : expm1f(o3);
    *(float4*)&out[(size_t)i * FOUT + f4] = make_float4(o0, o1, o2, o3);
}

// ---------------------------------------------------------------------------
extern "C" void kernel_launch(void* const* d_in, const int* in_sizes, int n_in,
                              void* d_out, int out_size) {
    const float* h = (const float*)d_in[0];
    const int* adj = (const int*)d_in[1];
    const float* W = (const float*)d_in[2];
    const float* a = (const float*)d_in[3];
    float* out = (float*)d_out;

    wh_kernel<<<N / 16, 256>>>(h, W);
    fvec_kernel<<<N / 256, 256>>>(a);
    bfrag_kernel<<<512, 256>>>();
    gat_mma_kernel<<<(N / NTILE) * NSPLIT, 256>>>(adj);
    fixup_kernel<<<N * 16 / 256, 256>>>(out);
}